// round 1
// baseline (speedup 1.0000x reference)
#include <cuda_runtime.h>
#include <cstdint>

#define M_DIM 2048
#define N_DIM 4096
#define K_DIM 4096

// Scratch (static device globals — no allocation at runtime)
__device__ float g_W[(size_t)N_DIM * K_DIM];   // transcribed weight, tf32-rounded
__device__ float g_X[(size_t)M_DIM * K_DIM];   // x, tf32-rounded

__device__ __forceinline__ uint32_t tf32_rna(float x) {
    uint32_t u;
    asm("cvt.rna.tf32.f32 %0, %1;" : "=r"(u) : "f"(x));
    return u;
}

// ---------------------------------------------------------------------------
// Kernel 1: fractal transcription  w <- a*w + b*sin(w), 20 iters, then tf32-round
// ---------------------------------------------------------------------------
__global__ void transcribe_k(const float* __restrict__ seed,
                             const float* __restrict__ da,
                             const float* __restrict__ db,
                             int niter) {
    __shared__ float sa[32], sb[32];
    if (threadIdx.x < 32 && threadIdx.x < niter) {
        sa[threadIdx.x] = da[threadIdx.x];
        sb[threadIdx.x] = db[threadIdx.x];
    }
    __syncthreads();

    size_t i = ((size_t)blockIdx.x * blockDim.x + threadIdx.x) * 4;
    if (i >= (size_t)N_DIM * K_DIM) return;

    float4 w = *reinterpret_cast<const float4*>(seed + i);
    #pragma unroll 20
    for (int k = 0; k < niter; k++) {
        float a = sa[k], b = sb[k];
        w.x = fmaf(b, __sinf(w.x), a * w.x);
        w.y = fmaf(b, __sinf(w.y), a * w.y);
        w.z = fmaf(b, __sinf(w.z), a * w.z);
        w.w = fmaf(b, __sinf(w.w), a * w.w);
    }
    float4 o;
    o.x = __uint_as_float(tf32_rna(w.x));
    o.y = __uint_as_float(tf32_rna(w.y));
    o.z = __uint_as_float(tf32_rna(w.z));
    o.w = __uint_as_float(tf32_rna(w.w));
    *reinterpret_cast<float4*>(g_W + i) = o;
}

// ---------------------------------------------------------------------------
// Kernel 2: tf32-round x into scratch
// ---------------------------------------------------------------------------
__global__ void convx_k(const float* __restrict__ x) {
    size_t i = ((size_t)blockIdx.x * blockDim.x + threadIdx.x) * 4;
    if (i >= (size_t)M_DIM * K_DIM) return;
    float4 v = *reinterpret_cast<const float4*>(x + i);
    float4 o;
    o.x = __uint_as_float(tf32_rna(v.x));
    o.y = __uint_as_float(tf32_rna(v.y));
    o.z = __uint_as_float(tf32_rna(v.z));
    o.w = __uint_as_float(tf32_rna(v.w));
    *reinterpret_cast<float4*>(g_X + i) = o;
}

// ---------------------------------------------------------------------------
// Kernel 3: TF32 tensor-core GEMM   out[m,n] = sum_k X[m,k]*W[n,k] + bias[n]
//   CTA tile 128x128, BK=16, 8 warps (2x4), warp tile 64x32,
//   double-buffered cp.async, m16n8k8 tf32 mma, fp32 accumulate.
// ---------------------------------------------------------------------------
#define BM 128
#define BN 128
#define BK 16
#define SSTRIDE 20              // 16 + 4 pad floats (keeps 16B align, no bank conflicts)
#define STAGE_F (128 * SSTRIDE) // 2560 floats = 10KB per operand per stage

__device__ __forceinline__ void cp16(float* sdst, const float* gsrc) {
    uint32_t sa = (uint32_t)__cvta_generic_to_shared(sdst);
    asm volatile("cp.async.cg.shared.global [%0], [%1], 16;\n" :: "r"(sa), "l"(gsrc));
}

__global__ __launch_bounds__(256, 2)
void gemm_tf32(const float* __restrict__ bias, float* __restrict__ C) {
    __shared__ float smem[4 * STAGE_F];   // As0 As1 Bs0 Bs1 = 40KB
    float* As[2] = { smem, smem + STAGE_F };
    float* Bs[2] = { smem + 2 * STAGE_F, smem + 3 * STAGE_F };

    const int tid  = threadIdx.x;
    const int lane = tid & 31;
    const int wid  = tid >> 5;
    const int warp_m = (wid >> 2) * 64;   // {0,64}
    const int warp_n = (wid & 3) * 32;    // {0,32,64,96}
    const int gid = lane >> 2;            // 0..7
    const int tig = lane & 3;             // 0..3
    const int cta_m = blockIdx.y * BM;
    const int cta_n = blockIdx.x * BN;

    // Global-load mapping: tile is 128 rows x 16 floats = 512 float4.
    // Thread t handles float4 #t and #(t+256): row = idx/4, col4 = idx%4.
    const int r0 = tid >> 2;              // 0..63
    const int c0 = (tid & 3) * 4;         // 0,4,8,12
    const float* gA0 = g_X + (size_t)(cta_m + r0)      * K_DIM + c0;
    const float* gA1 = g_X + (size_t)(cta_m + r0 + 64) * K_DIM + c0;
    const float* gB0 = g_W + (size_t)(cta_n + r0)      * K_DIM + c0;
    const float* gB1 = g_W + (size_t)(cta_n + r0 + 64) * K_DIM + c0;

    float acc[4][4][4];
    #pragma unroll
    for (int a = 0; a < 4; a++)
        #pragma unroll
        for (int b = 0; b < 4; b++)
            #pragma unroll
            for (int c = 0; c < 4; c++) acc[a][b][c] = 0.f;

    const int T = K_DIM / BK;   // 256 k-tiles

    // prologue: stage 0
    {
        cp16(As[0] + r0 * SSTRIDE + c0,        gA0);
        cp16(As[0] + (r0 + 64) * SSTRIDE + c0, gA1);
        cp16(Bs[0] + r0 * SSTRIDE + c0,        gB0);
        cp16(Bs[0] + (r0 + 64) * SSTRIDE + c0, gB1);
        asm volatile("cp.async.commit_group;\n");
    }

    for (int t = 0; t < T; t++) {
        const int s = t & 1;
        if (t + 1 < T) {
            const int k0 = (t + 1) * BK;
            float* a_dst = As[s ^ 1];
            float* b_dst = Bs[s ^ 1];
            cp16(a_dst + r0 * SSTRIDE + c0,        gA0 + k0);
            cp16(a_dst + (r0 + 64) * SSTRIDE + c0, gA1 + k0);
            cp16(b_dst + r0 * SSTRIDE + c0,        gB0 + k0);
            cp16(b_dst + (r0 + 64) * SSTRIDE + c0, gB1 + k0);
            asm volatile("cp.async.commit_group;\n");
            asm volatile("cp.async.wait_group 1;\n" ::: "memory");
        } else {
            asm volatile("cp.async.wait_group 0;\n" ::: "memory");
        }
        __syncthreads();

        const float* Ab = As[s];
        const float* Bb = Bs[s];
        #pragma unroll
        for (int ks = 0; ks < 2; ks++) {
            uint32_t afr[4][4], bfr[4][2];
            #pragma unroll
            for (int fm = 0; fm < 4; fm++) {
                const float* ap = Ab + (warp_m + fm * 16 + gid) * SSTRIDE + ks * 8 + tig;
                afr[fm][0] = __float_as_uint(ap[0]);
                afr[fm][1] = __float_as_uint(ap[8 * SSTRIDE]);
                afr[fm][2] = __float_as_uint(ap[4]);
                afr[fm][3] = __float_as_uint(ap[8 * SSTRIDE + 4]);
            }
            #pragma unroll
            for (int fn = 0; fn < 4; fn++) {
                const float* bp = Bb + (warp_n + fn * 8 + gid) * SSTRIDE + ks * 8 + tig;
                bfr[fn][0] = __float_as_uint(bp[0]);
                bfr[fn][1] = __float_as_uint(bp[4]);
            }
            #pragma unroll
            for (int fm = 0; fm < 4; fm++)
                #pragma unroll
                for (int fn = 0; fn < 4; fn++)
                    asm volatile(
                        "mma.sync.aligned.m16n8k8.row.col.f32.tf32.tf32.f32 "
                        "{%0,%1,%2,%3},{%4,%5,%6,%7},{%8,%9},{%0,%1,%2,%3};"
                        : "+f"(acc[fm][fn][0]), "+f"(acc[fm][fn][1]),
                          "+f"(acc[fm][fn][2]), "+f"(acc[fm][fn][3])
                        : "r"(afr[fm][0]), "r"(afr[fm][1]),
                          "r"(afr[fm][2]), "r"(afr[fm][3]),
                          "r"(bfr[fn][0]), "r"(bfr[fn][1]));
        }
        __syncthreads();
    }

    // Epilogue: add bias, store fp32
    #pragma unroll
    for (int fm = 0; fm < 4; fm++) {
        const int row = cta_m + warp_m + fm * 16 + gid;
        #pragma unroll
        for (int fn = 0; fn < 4; fn++) {
            const int col = cta_n + warp_n + fn * 8 + tig * 2;
            const float b0 = __ldg(&bias[col]);
            const float b1 = __ldg(&bias[col + 1]);
            float2 v0 = make_float2(acc[fm][fn][0] + b0, acc[fm][fn][1] + b1);
            float2 v1 = make_float2(acc[fm][fn][2] + b0, acc[fm][fn][3] + b1);
            *reinterpret_cast<float2*>(C + (size_t)row * N_DIM + col)       = v0;
            *reinterpret_cast<float2*>(C + (size_t)(row + 8) * N_DIM + col) = v1;
        }
    }
}

// ---------------------------------------------------------------------------
extern "C" void kernel_launch(void* const* d_in, const int* in_sizes, int n_in,
                              void* d_out, int out_size) {
    const float* x    = (const float*)d_in[0];   // [2048, 4096]
    const float* seed = (const float*)d_in[1];   // [4096, 4096]
    const float* da   = (const float*)d_in[2];   // [20]
    const float* db   = (const float*)d_in[3];   // [20]
    const float* bias = (const float*)d_in[4];   // [4096]
    float* out = (float*)d_out;                  // [2048, 4096]
    const int niter = in_sizes[2];

    transcribe_k<<<(N_DIM * (size_t)K_DIM / 4 + 255) / 256, 256>>>(seed, da, db, niter);
    convx_k<<<(M_DIM * (size_t)K_DIM / 4 + 255) / 256, 256>>>(x);

    dim3 grid(N_DIM / BN, M_DIM / BM);   // (32, 16)
    gemm_tf32<<<grid, 256>>>(bias, out);
}

// round 3
// speedup vs baseline: 3.1092x; 3.1092x over previous
#include <cuda.h>
#include <cuda_runtime.h>
#include <cuda_fp16.h>
#include <cstdint>

#define M_DIM 2048
#define N_DIM 4096
#define K_DIM 4096

// ---------------- scratch (static device globals; no runtime alloc) -------
__device__ __half g_Wh[(size_t)N_DIM * K_DIM];   // transcribed weight, fp16
__device__ __half g_Xh[(size_t)M_DIM * K_DIM];   // x, fp16

// ---------------- PTX helpers ----------------------------------------------
__device__ __forceinline__ uint32_t smem_u32(const void* p) {
    uint32_t a;
    asm("{ .reg .u64 t; cvta.to.shared.u64 t, %1; cvt.u32.u64 %0, t; }" : "=r"(a) : "l"(p));
    return a;
}
#define MBAR_INIT(a, n) \
    asm volatile("mbarrier.init.shared.b64 [%0], %1;" :: "r"(a), "r"((uint32_t)(n)) : "memory")
#define MBAR_EXPECT_TX(a, b) \
    asm volatile("mbarrier.arrive.expect_tx.shared.b64 _, [%0], %1;" :: "r"(a), "r"((uint32_t)(b)) : "memory")
#define MBAR_ARRIVE(a) \
    asm volatile("mbarrier.arrive.shared.b64 _, [%0];" :: "r"(a) : "memory")
#define MBAR_WAIT(a, ph) do {                                                   \
    uint32_t _m = (a); uint32_t _p = (ph); uint32_t _d;                         \
    asm volatile("{\n\t.reg .pred p;\n\t"                                       \
        "mbarrier.try_wait.parity.acquire.cta.shared::cta.b64 p, [%1], %2;\n\t" \
        "selp.b32 %0, 1, 0, p;\n\t}"                                            \
        : "=r"(_d) : "r"(_m), "r"(_p) : "memory");                              \
    if (!_d) {                                                                  \
        asm volatile("{\n\t.reg .pred P1;\n\t"                                  \
            "WL_%=:\n\t"                                                        \
            "mbarrier.try_wait.parity.acquire.cta.shared::cta.b64 P1, [%0], %1, 0x989680;\n\t" \
            "@P1 bra.uni WD_%=;\n\t"                                            \
            "bra.uni WL_%=;\n\t"                                                \
            "WD_%=:\n\t}" :: "r"(_m), "r"(_p) : "memory");                      \
    } } while (0)
#define TMA_LOAD_3D(smem_addr, map, cx, cy, cz, bar)                            \
    asm volatile("cp.async.bulk.tensor.3d.shared::cta.global.tile"              \
        ".mbarrier::complete_tx::bytes "                                        \
        "[%0], [%1, {%2, %3, %4}], [%5];"                                       \
        :: "r"((uint32_t)(smem_addr)), "l"(map),                                \
           "r"((int32_t)(cx)), "r"((int32_t)(cy)), "r"((int32_t)(cz)),          \
           "r"((uint32_t)(bar)) : "memory")

__device__ __forceinline__ void ldsm_x4(uint32_t (&r)[4], uint32_t addr) {
    asm volatile("ldmatrix.sync.aligned.m8n8.x4.shared.b16 {%0,%1,%2,%3}, [%4];"
        : "=r"(r[0]), "=r"(r[1]), "=r"(r[2]), "=r"(r[3]) : "r"(addr));
}
__device__ __forceinline__ void mma16816(float (&d)[4], const uint32_t (&a)[4],
                                         uint32_t b0, uint32_t b1) {
    asm volatile("mma.sync.aligned.m16n8k16.row.col.f32.f16.f16.f32 "
        "{%0,%1,%2,%3},{%4,%5,%6,%7},{%8,%9},{%0,%1,%2,%3};"
        : "+f"(d[0]), "+f"(d[1]), "+f"(d[2]), "+f"(d[3])
        : "r"(a[0]), "r"(a[1]), "r"(a[2]), "r"(a[3]), "r"(b0), "r"(b1));
}

// ---------------------------------------------------------------------------
// Kernel 1 (fused): fractal transcription of W (fp16 out) + fp16-round of X
// ---------------------------------------------------------------------------
#define NW4 ((size_t)N_DIM * K_DIM / 4)
#define NX4 ((size_t)M_DIM * K_DIM / 4)

__global__ void prep_k(const float* __restrict__ seed,
                       const float* __restrict__ x,
                       const float* __restrict__ da,
                       const float* __restrict__ db,
                       int niter) {
    __shared__ float sa[32], sb[32];
    if (threadIdx.x < 32 && threadIdx.x < niter) {
        sa[threadIdx.x] = da[threadIdx.x];
        sb[threadIdx.x] = db[threadIdx.x];
    }
    __syncthreads();

    size_t gid = (size_t)blockIdx.x * blockDim.x + threadIdx.x;
    if (gid < NW4) {
        size_t i = gid * 4;
        float4 w = *reinterpret_cast<const float4*>(seed + i);
        #pragma unroll 20
        for (int k = 0; k < niter; k++) {
            float a = sa[k], b = sb[k];
            w.x = fmaf(b, __sinf(w.x), a * w.x);
            w.y = fmaf(b, __sinf(w.y), a * w.y);
            w.z = fmaf(b, __sinf(w.z), a * w.z);
            w.w = fmaf(b, __sinf(w.w), a * w.w);
        }
        __half2 h0 = __floats2half2_rn(w.x, w.y);
        __half2 h1 = __floats2half2_rn(w.z, w.w);
        *reinterpret_cast<uint2*>(g_Wh + i) =
            make_uint2(*(uint32_t*)&h0, *(uint32_t*)&h1);
    } else if (gid < NW4 + NX4) {
        size_t i = (gid - NW4) * 4;
        float4 v = *reinterpret_cast<const float4*>(x + i);
        __half2 h0 = __floats2half2_rn(v.x, v.y);
        __half2 h1 = __floats2half2_rn(v.z, v.w);
        *reinterpret_cast<uint2*>(g_Xh + i) =
            make_uint2(*(uint32_t*)&h0, *(uint32_t*)&h1);
    }
}

// ---------------------------------------------------------------------------
// Kernel 2: fp16 mma.sync GEMM, TMA + 4-stage mbarrier pipeline.
//   CTA tile 128x256, BK=64. 8 compute warps (64x64 each) + 1 producer warp.
// ---------------------------------------------------------------------------
#define NSTAGES 4
#define BK      64
#define ITERS   (K_DIM / BK)             // 64
#define A_BYTES (128 * 128)              // 128 rows x 64 halves(128B) = 16KB
#define B_BYTES (256 * 128)              // 32KB
#define STAGE_BYTES (A_BYTES + B_BYTES)  // 48KB
#define DYN_SMEM (NSTAGES * STAGE_BYTES + 1024)

__global__ void __launch_bounds__(288, 1)
gemm_fp16(const __grid_constant__ CUtensorMap tma_a,
          const __grid_constant__ CUtensorMap tma_b,
          const float* __restrict__ bias,
          float* __restrict__ out) {
    extern __shared__ char dsm[];
    __shared__ uint64_t bars[2 * NSTAGES];   // full[0..3], empty[0..3]

    const uint32_t tiles = (smem_u32(dsm) + 1023u) & ~1023u;
    const uint32_t bar0 = smem_u32(bars);
    const int tid = threadIdx.x;
    const int wid = tid >> 5;
    const int lane = tid & 31;
    const int cta_m = blockIdx.y * 128;
    const int cta_n = blockIdx.x * 256;

    if (tid == 0) {
        #pragma unroll
        for (int s = 0; s < NSTAGES; s++) {
            MBAR_INIT(bar0 + s * 8, 1);               // full: tx-based
            MBAR_INIT(bar0 + (NSTAGES + s) * 8, 8);   // empty: 8 compute warps
        }
    }
    __syncthreads();

    if (wid == 8) {
        // ---------------- producer warp (lane 0 only) ----------------
        if (lane == 0) {
            for (int t = 0; t < ITERS; t++) {
                const int s = t & 3;
                if (t >= NSTAGES)
                    MBAR_WAIT(bar0 + (NSTAGES + s) * 8, ((t >> 2) - 1) & 1);
                MBAR_EXPECT_TX(bar0 + s * 8, STAGE_BYTES);
                const uint32_t st = tiles + s * STAGE_BYTES;
                TMA_LOAD_3D(st,           &tma_a, t * BK, cta_m, 0, bar0 + s * 8);
                TMA_LOAD_3D(st + A_BYTES, &tma_b, t * BK, cta_n, 0, bar0 + s * 8);
            }
        }
        return;
    }

    // ---------------- compute warps ----------------
    const int warp_m = (wid >> 2) * 64;      // {0, 64}
    const int warp_n = (wid & 3) * 64;       // {0, 64, 128, 192}

    // ldmatrix lane addressing (SW128 swizzle: off ^ ((row&7)<<4), row stride 128B)
    // A: lanes 0-15 -> rows m+0..15 @k16=0 ; lanes 16-31 -> same rows @k16=16B
    const int a_row_l = (lane & 15);
    const int a_k16   = (lane >> 4) * 16;
    // B: lanes 0-7 n+0..7 @0 ; 8-15 n+0..7 @16 ; 16-23 n+8..15 @0 ; 24-31 n+8..15 @16
    const int b_row_l = (lane & 7) + ((lane >> 4) << 3);
    const int b_k16   = ((lane >> 3) & 1) * 16;

    uint32_t a_base[4], a_xor[4];
    #pragma unroll
    for (int fm = 0; fm < 4; fm++) {
        int r = warp_m + fm * 16 + a_row_l;
        a_base[fm] = r * 128;
        a_xor[fm] = (r & 7) << 4;
    }
    uint32_t b_base[4], b_xor[4];
    #pragma unroll
    for (int fn2 = 0; fn2 < 4; fn2++) {
        int r = warp_n + fn2 * 16 + b_row_l;
        b_base[fn2] = r * 128;
        b_xor[fn2] = (r & 7) << 4;
    }

    float acc[4][8][4];
    #pragma unroll
    for (int i = 0; i < 4; i++)
        #pragma unroll
        for (int j = 0; j < 8; j++)
            #pragma unroll
            for (int c = 0; c < 4; c++) acc[i][j][c] = 0.f;

    for (int t = 0; t < ITERS; t++) {
        const int s = t & 3;
        MBAR_WAIT(bar0 + s * 8, (t >> 2) & 1);
        const uint32_t sa = tiles + s * STAGE_BYTES;
        const uint32_t sb = sa + A_BYTES;

        #pragma unroll
        for (int ks = 0; ks < 4; ks++) {
            uint32_t af[4][4], bf[4][4];
            #pragma unroll
            for (int fm = 0; fm < 4; fm++)
                ldsm_x4(af[fm], sa + a_base[fm] + ((ks * 32 + a_k16) ^ a_xor[fm]));
            #pragma unroll
            for (int fn2 = 0; fn2 < 4; fn2++)
                ldsm_x4(bf[fn2], sb + b_base[fn2] + ((ks * 32 + b_k16) ^ b_xor[fn2]));
            #pragma unroll
            for (int fm = 0; fm < 4; fm++)
                #pragma unroll
                for (int fn2 = 0; fn2 < 4; fn2++) {
                    mma16816(acc[fm][2 * fn2],     af[fm], bf[fn2][0], bf[fn2][1]);
                    mma16816(acc[fm][2 * fn2 + 1], af[fm], bf[fn2][2], bf[fn2][3]);
                }
        }
        if (lane == 0) MBAR_ARRIVE(bar0 + (NSTAGES + s) * 8);
    }

    // ---------------- epilogue: bias add + store ----------------
    const int gid4 = lane >> 2;      // 0..7
    const int tig  = lane & 3;       // 0..3
    #pragma unroll
    for (int fm = 0; fm < 4; fm++) {
        const int row = cta_m + warp_m + fm * 16 + gid4;
        #pragma unroll
        for (int fn = 0; fn < 8; fn++) {
            const int col = cta_n + warp_n + fn * 8 + tig * 2;
            const float b0 = __ldg(&bias[col]);
            const float b1 = __ldg(&bias[col + 1]);
            float2 v0 = make_float2(acc[fm][fn][0] + b0, acc[fm][fn][1] + b1);
            float2 v1 = make_float2(acc[fm][fn][2] + b0, acc[fm][fn][3] + b1);
            *reinterpret_cast<float2*>(out + (size_t)row * N_DIM + col)       = v0;
            *reinterpret_cast<float2*>(out + (size_t)(row + 8) * N_DIM + col) = v1;
        }
    }
}

// ---------------------------------------------------------------------------
typedef CUresult (*tmap_fn)(CUtensorMap*, CUtensorMapDataType, cuuint32_t, void*,
                            const cuuint64_t*, const cuuint64_t*, const cuuint32_t*,
                            const cuuint32_t*, CUtensorMapInterleave, CUtensorMapSwizzle,
                            CUtensorMapL2promotion, CUtensorMapFloatOOBfill);

static void make_map(tmap_fn enc, CUtensorMap* m, void* base, uint64_t rows,
                     uint32_t box_rows) {
    cuuint64_t dims[3]    = {K_DIM, rows, 1};
    cuuint64_t strides[2] = {K_DIM * 2ull, rows * K_DIM * 2ull};
    cuuint32_t box[3]     = {64, box_rows, 1};   // 64 halves = 128B (SW128)
    cuuint32_t es[3]      = {1, 1, 1};
    enc(m, CU_TENSOR_MAP_DATA_TYPE_FLOAT16, 3, base, dims, strides, box, es,
        CU_TENSOR_MAP_INTERLEAVE_NONE, CU_TENSOR_MAP_SWIZZLE_128B,
        CU_TENSOR_MAP_L2_PROMOTION_L2_128B, CU_TENSOR_MAP_FLOAT_OOB_FILL_NONE);
}

extern "C" void kernel_launch(void* const* d_in, const int* in_sizes, int n_in,
                              void* d_out, int out_size) {
    const float* x    = (const float*)d_in[0];   // [2048, 4096]
    const float* seed = (const float*)d_in[1];   // [4096, 4096]
    const float* da   = (const float*)d_in[2];   // [20]
    const float* db   = (const float*)d_in[3];   // [20]
    const float* bias = (const float*)d_in[4];   // [4096]
    float* out = (float*)d_out;                  // [2048, 4096]
    const int niter = in_sizes[2];

    void* pW = nullptr; void* pX = nullptr;
    cudaGetSymbolAddress(&pW, g_Wh);
    cudaGetSymbolAddress(&pX, g_Xh);

    tmap_fn enc = nullptr;
    cudaDriverEntryPointQueryResult qr;
    cudaGetDriverEntryPointByVersion("cuTensorMapEncodeTiled", (void**)&enc, 12000,
                                     cudaEnableDefault, &qr);

    CUtensorMap map_a, map_b;
    make_map(enc, &map_a, pX, M_DIM, 128);   // A = X
    make_map(enc, &map_b, pW, N_DIM, 256);   // B = W

    const size_t total4 = NW4 + NX4;
    prep_k<<<(unsigned)((total4 + 255) / 256), 256>>>(seed, x, da, db, niter);

    cudaFuncSetAttribute(gemm_fp16, cudaFuncAttributeMaxDynamicSharedMemorySize, DYN_SMEM);
    dim3 grid(N_DIM / 256, M_DIM / 128);     // (16, 16)
    gemm_fp16<<<grid, 288, DYN_SMEM>>>(map_a, map_b, bias, out);
}